// round 4
// baseline (speedup 1.0000x reference)
#include <cuda_runtime.h>

#define NN 50000
#define NE 800000
#define D  128
#define NG 512
#define AS 132   // As row stride (floats)

// Scratch (no device allocation allowed -> __device__ globals)
__device__ __align__(16) float g_agg[NN * D];
__device__ __align__(16) float g_t  [NN * D];
__device__ __align__(16) float g_h  [NN * D];
__device__ __align__(16) float g_pool[NG * D];
__device__ int g_deg[NN];
__device__ int g_rowptr[NN + 1];
__device__ int g_cursor[NN];
__device__ int g_csr[NE];

// ---------------------------------------------------------------------------
__global__ void zero_kernel(float* __restrict__ p, int n4) {
    float4 z = make_float4(0.f, 0.f, 0.f, 0.f);
    for (int i = blockIdx.x * blockDim.x + threadIdx.x; i < n4;
         i += gridDim.x * blockDim.x)
        reinterpret_cast<float4*>(p)[i] = z;
}
__global__ void zeroi_kernel(int* __restrict__ p, int n) {
    for (int i = blockIdx.x * blockDim.x + threadIdx.x; i < n;
         i += gridDim.x * blockDim.x) p[i] = 0;
}

// ---------------------------------------------------------------------------
// CSR build: histogram -> scan -> fill
__global__ void hist_kernel(const int* __restrict__ dst, int* __restrict__ deg) {
    for (int e = blockIdx.x * blockDim.x + threadIdx.x; e < NE;
         e += gridDim.x * blockDim.x)
        atomicAdd(&deg[dst[e]], 1);
}

#define SCAN_T 1024
#define SCAN_CH 49   // 1024*49 = 50176 >= NN+1
__global__ void scan_kernel(const int* __restrict__ deg,
                            int* __restrict__ rowptr,
                            int* __restrict__ cursor) {
    __shared__ int part[SCAN_T];
    int t = threadIdx.x;
    int base = t * SCAN_CH;
    int s = 0;
#pragma unroll
    for (int i = 0; i < SCAN_CH; i++) {
        int idx = base + i;
        if (idx < NN) s += deg[idx];
    }
    part[t] = s;
    __syncthreads();
    for (int d = 1; d < SCAN_T; d <<= 1) {
        int v = (t >= d) ? part[t - d] : 0;
        __syncthreads();
        part[t] += v;
        __syncthreads();
    }
    int run = part[t] - s;   // exclusive offset
    for (int i = 0; i < SCAN_CH; i++) {
        int idx = base + i;
        if (idx <= NN) {
            rowptr[idx] = run;
            if (idx < NN) {
                cursor[idx] = run;
                run += deg[idx];
            }
        }
    }
}

__global__ void fill_kernel(const int* __restrict__ src,
                            const int* __restrict__ dst,
                            int* __restrict__ cursor,
                            int* __restrict__ csr) {
    for (int e = blockIdx.x * blockDim.x + threadIdx.x; e < NE;
         e += gridDim.x * blockDim.x) {
        int d = dst[e];
        int pos = atomicAdd(&cursor[d], 1);
        csr[pos] = src[e];
    }
}

// ---------------------------------------------------------------------------
// CSR aggregate: warp per node, z[n] = h[n] + sum_{s in N(n)} h[s]
// No atomics, no zeroing; software-pipelined gathers (MLP>=2).
__global__ void agg_kernel(const float* __restrict__ hin,
                           const int* __restrict__ rowptr,
                           const int* __restrict__ csr,
                           float* __restrict__ out) {
    int lane = threadIdx.x & 31;
    int warp = (blockIdx.x * blockDim.x + threadIdx.x) >> 5;
    int nwarp = (gridDim.x * blockDim.x) >> 5;
    for (int n = warp; n < NN; n += nwarp) {
        int beg = rowptr[n], end = rowptr[n + 1];
        float4 acc = *reinterpret_cast<const float4*>(hin + (size_t)n * D + lane * 4);
        for (int j0 = beg; j0 < end; j0 += 32) {
            int m = min(32, end - j0);
            int idx = (j0 + lane < end) ? csr[j0 + lane] : 0;
            int s0 = __shfl_sync(0xffffffffu, idx, 0);
            float4 v = *reinterpret_cast<const float4*>(hin + (size_t)s0 * D + lane * 4);
            for (int k = 1; k < m; k++) {
                int sk = __shfl_sync(0xffffffffu, idx, k);
                float4 v2 = *reinterpret_cast<const float4*>(hin + (size_t)sk * D + lane * 4);
                acc.x += v.x; acc.y += v.y; acc.z += v.z; acc.w += v.w;
                v = v2;
            }
            acc.x += v.x; acc.y += v.y; acc.z += v.z; acc.w += v.w;
        }
        *reinterpret_cast<float4*>(out + (size_t)n * D + lane * 4) = acc;
    }
}

// ---------------------------------------------------------------------------
__global__ void pool_kernel(const float* __restrict__ hin,
                            const int* __restrict__ batch,
                            float* __restrict__ pool) {
    int lane = threadIdx.x & 31;
    int warp = (blockIdx.x * blockDim.x + threadIdx.x) >> 5;
    int nwarp = (gridDim.x * blockDim.x) >> 5;
    for (int n = warp; n < NN; n += nwarp) {
        int b = 0;
        if (lane == 0) b = batch[n];
        b = __shfl_sync(0xffffffffu, b, 0);
        float4 v = *reinterpret_cast<const float4*>(hin + (size_t)n * D + lane * 4);
        float* p = pool + (size_t)b * D + lane * 4;
        asm volatile("red.global.add.v4.f32 [%0], {%1,%2,%3,%4};"
                     :: "l"(p), "f"(v.x), "f"(v.y), "f"(v.z), "f"(v.w)
                     : "memory");
    }
}

// ---------------------------------------------------------------------------
// Packed f32x2 helpers (sm_103a FFMA2, PTX-only)
__device__ __forceinline__ unsigned long long pk2(float x, float y) {
    unsigned long long r;
    asm("mov.b64 %0, {%1, %2};" : "=l"(r) : "f"(x), "f"(y));
    return r;
}
__device__ __forceinline__ void upk2(unsigned long long v, float& x, float& y) {
    asm("mov.b64 {%0, %1}, %2;" : "=f"(x), "=f"(y) : "l"(v));
}
#define FMA2(d, a, b) \
    asm("fma.rn.f32x2 %0, %1, %2, %0;" : "+l"(d) : "l"(a), "l"(b))

// ---------------------------------------------------------------------------
// Persistent GEMM: out = relu(A @ W + bias). 64x128 tile, 4x8/thread, FMA2.
// 2 CTAs/SM (97KB smem each) -> 16 warps/SM for latency hiding.
__global__ __launch_bounds__(256, 2)
void gemm_kernel(const float* __restrict__ A, const float* __restrict__ W,
                 const float* __restrict__ bias, float* __restrict__ out,
                 int M) {
    extern __shared__ float sm[];
    float* Ws = sm;                  // [128][128] = 64KB
    float* As = sm + 128 * 128;      // [64][AS]

    int tid = threadIdx.x;
    int tr = tid >> 4;               // rows tr*4..tr*4+3
    int tc = tid & 15;               // cols tc*8..tc*8+7

    // Load W once (16384 floats)
#pragma unroll
    for (int j = 0; j < 16; j++) {
        int i4 = tid + 256 * j;
        reinterpret_cast<float4*>(Ws)[i4] =
            reinterpret_cast<const float4*>(W)[i4];
    }

    float4 bb0 = *reinterpret_cast<const float4*>(bias + tc * 8);
    float4 bb1 = *reinterpret_cast<const float4*>(bias + tc * 8 + 4);
    float bs[8] = {bb0.x, bb0.y, bb0.z, bb0.w, bb1.x, bb1.y, bb1.z, bb1.w};

    int ntiles = (M + 63) >> 6;
    for (int tile = blockIdx.x; tile < ntiles; tile += gridDim.x) {
        int row0 = tile << 6;
        __syncthreads();
        // Load A tile: 64 rows x 32 float4 = 2048 float4
#pragma unroll
        for (int j = 0; j < 8; j++) {
            int i4 = tid + 256 * j;
            int r = i4 >> 5;
            int kq = i4 & 31;
            int gr = row0 + r;
            float4 v = make_float4(0.f, 0.f, 0.f, 0.f);
            if (gr < M)
                v = reinterpret_cast<const float4*>(A + (size_t)gr * D)[kq];
            *reinterpret_cast<float4*>(&As[r * AS + kq * 4]) = v;
        }
        __syncthreads();

        unsigned long long acc[4][4];
#pragma unroll
        for (int i = 0; i < 4; i++)
#pragma unroll
            for (int j = 0; j < 4; j++) acc[i][j] = 0ull;

        const float* arow = As + tr * 4 * AS;
#pragma unroll 8
        for (int k = 0; k < 128; k++) {
            float4 b0 = *reinterpret_cast<const float4*>(&Ws[k * 128 + tc * 8]);
            float4 b1 = *reinterpret_cast<const float4*>(&Ws[k * 128 + tc * 8 + 4]);
            unsigned long long bp0 = pk2(b0.x, b0.y);
            unsigned long long bp1 = pk2(b0.z, b0.w);
            unsigned long long bp2 = pk2(b1.x, b1.y);
            unsigned long long bp3 = pk2(b1.z, b1.w);
#pragma unroll
            for (int i = 0; i < 4; i++) {
                float a = arow[i * AS + k];
                unsigned long long aa = pk2(a, a);
                FMA2(acc[i][0], aa, bp0);
                FMA2(acc[i][1], aa, bp1);
                FMA2(acc[i][2], aa, bp2);
                FMA2(acc[i][3], aa, bp3);
            }
        }

#pragma unroll
        for (int i = 0; i < 4; i++) {
            int gr = row0 + tr * 4 + i;
            if (gr < M) {
                float o[8];
#pragma unroll
                for (int j = 0; j < 4; j++)
                    upk2(acc[i][j], o[2 * j], o[2 * j + 1]);
                float4 s0, s1;
                s0.x = fmaxf(o[0] + bs[0], 0.f);
                s0.y = fmaxf(o[1] + bs[1], 0.f);
                s0.z = fmaxf(o[2] + bs[2], 0.f);
                s0.w = fmaxf(o[3] + bs[3], 0.f);
                s1.x = fmaxf(o[4] + bs[4], 0.f);
                s1.y = fmaxf(o[5] + bs[5], 0.f);
                s1.z = fmaxf(o[6] + bs[6], 0.f);
                s1.w = fmaxf(o[7] + bs[7], 0.f);
                *reinterpret_cast<float4*>(out + (size_t)gr * D + tc * 8)     = s0;
                *reinterpret_cast<float4*>(out + (size_t)gr * D + tc * 8 + 4) = s1;
            }
        }
    }
}

// ---------------------------------------------------------------------------
extern "C" void kernel_launch(void* const* d_in, const int* in_sizes, int n_in,
                              void* d_out, int out_size) {
    const float* x = (const float*)d_in[0];
    const int* ei = (const int*)d_in[1];       // int32 (JAX x64 disabled)
    const int* batch = (const int*)d_in[2];    // int32
    const float* W1a = (const float*)d_in[3];
    const float* b1a = (const float*)d_in[4];
    const float* W1b = (const float*)d_in[5];
    const float* b1b = (const float*)d_in[6];
    const float* W2a = (const float*)d_in[7];
    const float* b2a = (const float*)d_in[8];
    const float* W2b = (const float*)d_in[9];
    const float* b2b = (const float*)d_in[10];
    const float* Wfc = (const float*)d_in[11];
    const float* bfc = (const float*)d_in[12];
    float* out = (float*)d_out;

    const int* src = ei;
    const int* dst = ei + NE;

    float *agg, *t, *h, *pool;
    int *deg, *rowptr, *cursor, *csr;
    cudaGetSymbolAddress((void**)&agg, g_agg);
    cudaGetSymbolAddress((void**)&t, g_t);
    cudaGetSymbolAddress((void**)&h, g_h);
    cudaGetSymbolAddress((void**)&pool, g_pool);
    cudaGetSymbolAddress((void**)&deg, g_deg);
    cudaGetSymbolAddress((void**)&rowptr, g_rowptr);
    cudaGetSymbolAddress((void**)&cursor, g_cursor);
    cudaGetSymbolAddress((void**)&csr, g_csr);

    const int SMEM = (128 * 128 + 64 * AS) * (int)sizeof(float); // 99328 B
    cudaFuncSetAttribute(gemm_kernel,
                         cudaFuncAttributeMaxDynamicSharedMemorySize, SMEM);

    int gemm_grid = 296;   // 2 CTAs per SM, persistent

    // CSR build (once per launch; reused by both layers)
    zeroi_kernel<<<256, 256>>>(deg, NN);
    hist_kernel<<<1024, 256>>>(dst, deg);
    scan_kernel<<<1, SCAN_T>>>(deg, rowptr, cursor);
    fill_kernel<<<1024, 256>>>(src, dst, cursor, csr);

    // Layer 1
    agg_kernel<<<2048, 256>>>(x, rowptr, csr, agg);
    gemm_kernel<<<gemm_grid, 256, SMEM>>>(agg, W1a, b1a, t, NN);
    gemm_kernel<<<gemm_grid, 256, SMEM>>>(t, W1b, b1b, h, NN);

    // Layer 2
    agg_kernel<<<2048, 256>>>(h, rowptr, csr, agg);
    gemm_kernel<<<gemm_grid, 256, SMEM>>>(agg, W2a, b2a, t, NN);
    gemm_kernel<<<gemm_grid, 256, SMEM>>>(t, W2b, b2b, h, NN);

    // Global add pool + FC head
    zero_kernel<<<64, 256>>>(pool, NG * D / 4);
    pool_kernel<<<2048, 256>>>(h, batch, pool);
    gemm_kernel<<<8, 256, SMEM>>>(pool, Wfc, bfc, out, NG);
}

// round 5
// speedup vs baseline: 1.2107x; 1.2107x over previous
#include <cuda_runtime.h>

#define NN 50000
#define NE 800000
#define D  128
#define NG 512
#define AS 132   // As row stride (floats)
#define NBLK 196 // ceil(NN/256) scan blocks

// Scratch (no device allocation allowed -> __device__ globals)
__device__ __align__(16) float g_agg[NN * D];
__device__ __align__(16) float g_t  [NN * D];
__device__ __align__(16) float g_h  [NN * D];
__device__ __align__(16) float g_pool[NG * D];
__device__ int g_deg[NN];
__device__ int g_rowptr[NN + 1];
__device__ int g_cursor[NN];
__device__ int g_csr[NE];
__device__ int g_bsum[NBLK];
__device__ int g_bbase[NBLK];

// ---------------------------------------------------------------------------
__global__ void zero_kernel(float* __restrict__ p, int n4) {
    float4 z = make_float4(0.f, 0.f, 0.f, 0.f);
    for (int i = blockIdx.x * blockDim.x + threadIdx.x; i < n4;
         i += gridDim.x * blockDim.x)
        reinterpret_cast<float4*>(p)[i] = z;
}
__global__ void zeroi_kernel(int* __restrict__ p, int n) {
    for (int i = blockIdx.x * blockDim.x + threadIdx.x; i < n;
         i += gridDim.x * blockDim.x) p[i] = 0;
}

// ---------------------------------------------------------------------------
// CSR build: histogram -> hierarchical scan -> fill
__global__ void hist_kernel(const int* __restrict__ dst, int* __restrict__ deg) {
    for (int e = blockIdx.x * blockDim.x + threadIdx.x; e < NE;
         e += gridDim.x * blockDim.x)
        atomicAdd(&deg[dst[e]], 1);
}

// Phase 1: per-block sums of deg (coalesced)
__global__ void bsum_kernel(const int* __restrict__ deg, int* __restrict__ bsum) {
    __shared__ int s[256];
    int i = blockIdx.x * 256 + threadIdx.x;
    s[threadIdx.x] = (i < NN) ? deg[i] : 0;
    __syncthreads();
    for (int d = 128; d > 0; d >>= 1) {
        if (threadIdx.x < d) s[threadIdx.x] += s[threadIdx.x + d];
        __syncthreads();
    }
    if (threadIdx.x == 0) bsum[blockIdx.x] = s[0];
}

// Phase 2: exclusive scan of NBLK block sums (single tiny block)
__global__ void bscan_kernel(const int* __restrict__ bsum, int* __restrict__ bbase) {
    __shared__ int s[256];
    int t = threadIdx.x;
    s[t] = (t < NBLK) ? bsum[t] : 0;
    __syncthreads();
    for (int d = 1; d < 256; d <<= 1) {
        int v = (t >= d) ? s[t - d] : 0;
        __syncthreads();
        s[t] += v;
        __syncthreads();
    }
    if (t < NBLK) bbase[t] = s[t] - bsum[t];  // exclusive
}

// Phase 3: intra-block exclusive scan + add block base -> rowptr & cursor
__global__ void rowptr_kernel(const int* __restrict__ deg,
                              const int* __restrict__ bbase,
                              int* __restrict__ rowptr,
                              int* __restrict__ cursor) {
    __shared__ int s[256];
    int t = threadIdx.x;
    int i = blockIdx.x * 256 + t;
    int d0 = (i < NN) ? deg[i] : 0;
    s[t] = d0;
    __syncthreads();
    for (int d = 1; d < 256; d <<= 1) {
        int v = (t >= d) ? s[t - d] : 0;
        __syncthreads();
        s[t] += v;
        __syncthreads();
    }
    if (i < NN) {
        int off = bbase[blockIdx.x] + s[t] - d0;  // exclusive prefix
        rowptr[i] = off;
        cursor[i] = off;
        if (i == NN - 1) rowptr[NN] = off + d0;
    }
}

__global__ void fill_kernel(const int* __restrict__ src,
                            const int* __restrict__ dst,
                            int* __restrict__ cursor,
                            int* __restrict__ csr) {
    for (int e = blockIdx.x * blockDim.x + threadIdx.x; e < NE;
         e += gridDim.x * blockDim.x) {
        int d = dst[e];
        int pos = atomicAdd(&cursor[d], 1);
        csr[pos] = src[e];
    }
}

// ---------------------------------------------------------------------------
// CSR aggregate: warp per node, z[n] = h[n] + sum_{s in N(n)} h[s].
// Broadcast csr loads (same addr across warp), 4-way unrolled gather with
// 4 independent accumulators -> MLP>=4, L2-throughput bound.
__global__ void agg_kernel(const float* __restrict__ hin,
                           const int* __restrict__ rowptr,
                           const int* __restrict__ csr,
                           float* __restrict__ out) {
    int lane = threadIdx.x & 31;
    int warp = (blockIdx.x * blockDim.x + threadIdx.x) >> 5;
    int nwarp = (gridDim.x * blockDim.x) >> 5;
    for (int n = warp; n < NN; n += nwarp) {
        int beg = __ldg(&rowptr[n]), end = __ldg(&rowptr[n + 1]);
        int off = lane * 4;
        float4 a0 = *reinterpret_cast<const float4*>(hin + (size_t)n * D + off);
        float4 a1 = make_float4(0.f, 0.f, 0.f, 0.f);
        float4 a2 = make_float4(0.f, 0.f, 0.f, 0.f);
        float4 a3 = make_float4(0.f, 0.f, 0.f, 0.f);
        int k = beg;
        for (; k + 4 <= end; k += 4) {
            int s0 = __ldg(&csr[k]);
            int s1 = __ldg(&csr[k + 1]);
            int s2 = __ldg(&csr[k + 2]);
            int s3 = __ldg(&csr[k + 3]);
            float4 v0 = *reinterpret_cast<const float4*>(hin + (size_t)s0 * D + off);
            float4 v1 = *reinterpret_cast<const float4*>(hin + (size_t)s1 * D + off);
            float4 v2 = *reinterpret_cast<const float4*>(hin + (size_t)s2 * D + off);
            float4 v3 = *reinterpret_cast<const float4*>(hin + (size_t)s3 * D + off);
            a0.x += v0.x; a0.y += v0.y; a0.z += v0.z; a0.w += v0.w;
            a1.x += v1.x; a1.y += v1.y; a1.z += v1.z; a1.w += v1.w;
            a2.x += v2.x; a2.y += v2.y; a2.z += v2.z; a2.w += v2.w;
            a3.x += v3.x; a3.y += v3.y; a3.z += v3.z; a3.w += v3.w;
        }
        for (; k < end; k++) {
            int s = __ldg(&csr[k]);
            float4 v = *reinterpret_cast<const float4*>(hin + (size_t)s * D + off);
            a0.x += v.x; a0.y += v.y; a0.z += v.z; a0.w += v.w;
        }
        a0.x += a1.x + a2.x + a3.x;
        a0.y += a1.y + a2.y + a3.y;
        a0.z += a1.z + a2.z + a3.z;
        a0.w += a1.w + a2.w + a3.w;
        *reinterpret_cast<float4*>(out + (size_t)n * D + off) = a0;
    }
}

// ---------------------------------------------------------------------------
__global__ void pool_kernel(const float* __restrict__ hin,
                            const int* __restrict__ batch,
                            float* __restrict__ pool) {
    int lane = threadIdx.x & 31;
    int warp = (blockIdx.x * blockDim.x + threadIdx.x) >> 5;
    int nwarp = (gridDim.x * blockDim.x) >> 5;
    for (int n = warp; n < NN; n += nwarp) {
        int b = __ldg(&batch[n]);
        float4 v = *reinterpret_cast<const float4*>(hin + (size_t)n * D + lane * 4);
        float* p = pool + (size_t)b * D + lane * 4;
        asm volatile("red.global.add.v4.f32 [%0], {%1,%2,%3,%4};"
                     :: "l"(p), "f"(v.x), "f"(v.y), "f"(v.z), "f"(v.w)
                     : "memory");
    }
}

// ---------------------------------------------------------------------------
// Packed f32x2 helpers (sm_103a FFMA2, PTX-only)
__device__ __forceinline__ unsigned long long pk2(float x, float y) {
    unsigned long long r;
    asm("mov.b64 %0, {%1, %2};" : "=l"(r) : "f"(x), "f"(y));
    return r;
}
__device__ __forceinline__ void upk2(unsigned long long v, float& x, float& y) {
    asm("mov.b64 {%0, %1}, %2;" : "=f"(x), "=f"(y) : "l"(v));
}
#define FMA2(d, a, b) \
    asm("fma.rn.f32x2 %0, %1, %2, %0;" : "+l"(d) : "l"(a), "l"(b))

// ---------------------------------------------------------------------------
// Persistent GEMM: out = relu(A @ W + bias). 64x128 tile, 4x8/thread, FMA2.
// 2 CTAs/SM (97KB smem each) -> 16 warps/SM.
__global__ __launch_bounds__(256, 2)
void gemm_kernel(const float* __restrict__ A, const float* __restrict__ W,
                 const float* __restrict__ bias, float* __restrict__ out,
                 int M) {
    extern __shared__ float sm[];
    float* Ws = sm;                  // [128][128] = 64KB
    float* As = sm + 128 * 128;      // [64][AS]

    int tid = threadIdx.x;
    int tr = tid >> 4;               // rows tr*4..tr*4+3
    int tc = tid & 15;               // cols tc*8..tc*8+7

#pragma unroll
    for (int j = 0; j < 16; j++) {
        int i4 = tid + 256 * j;
        reinterpret_cast<float4*>(Ws)[i4] =
            reinterpret_cast<const float4*>(W)[i4];
    }

    float4 bb0 = *reinterpret_cast<const float4*>(bias + tc * 8);
    float4 bb1 = *reinterpret_cast<const float4*>(bias + tc * 8 + 4);
    float bs[8] = {bb0.x, bb0.y, bb0.z, bb0.w, bb1.x, bb1.y, bb1.z, bb1.w};

    int ntiles = (M + 63) >> 6;
    for (int tile = blockIdx.x; tile < ntiles; tile += gridDim.x) {
        int row0 = tile << 6;
        __syncthreads();
#pragma unroll
        for (int j = 0; j < 8; j++) {
            int i4 = tid + 256 * j;
            int r = i4 >> 5;
            int kq = i4 & 31;
            int gr = row0 + r;
            float4 v = make_float4(0.f, 0.f, 0.f, 0.f);
            if (gr < M)
                v = reinterpret_cast<const float4*>(A + (size_t)gr * D)[kq];
            *reinterpret_cast<float4*>(&As[r * AS + kq * 4]) = v;
        }
        __syncthreads();

        unsigned long long acc[4][4];
#pragma unroll
        for (int i = 0; i < 4; i++)
#pragma unroll
            for (int j = 0; j < 4; j++) acc[i][j] = 0ull;

        const float* arow = As + tr * 4 * AS;
#pragma unroll 8
        for (int k = 0; k < 128; k++) {
            float4 b0 = *reinterpret_cast<const float4*>(&Ws[k * 128 + tc * 8]);
            float4 b1 = *reinterpret_cast<const float4*>(&Ws[k * 128 + tc * 8 + 4]);
            unsigned long long bp0 = pk2(b0.x, b0.y);
            unsigned long long bp1 = pk2(b0.z, b0.w);
            unsigned long long bp2 = pk2(b1.x, b1.y);
            unsigned long long bp3 = pk2(b1.z, b1.w);
#pragma unroll
            for (int i = 0; i < 4; i++) {
                float a = arow[i * AS + k];
                unsigned long long aa = pk2(a, a);
                FMA2(acc[i][0], aa, bp0);
                FMA2(acc[i][1], aa, bp1);
                FMA2(acc[i][2], aa, bp2);
                FMA2(acc[i][3], aa, bp3);
            }
        }

#pragma unroll
        for (int i = 0; i < 4; i++) {
            int gr = row0 + tr * 4 + i;
            if (gr < M) {
                float o[8];
#pragma unroll
                for (int j = 0; j < 4; j++)
                    upk2(acc[i][j], o[2 * j], o[2 * j + 1]);
                float4 s0, s1;
                s0.x = fmaxf(o[0] + bs[0], 0.f);
                s0.y = fmaxf(o[1] + bs[1], 0.f);
                s0.z = fmaxf(o[2] + bs[2], 0.f);
                s0.w = fmaxf(o[3] + bs[3], 0.f);
                s1.x = fmaxf(o[4] + bs[4], 0.f);
                s1.y = fmaxf(o[5] + bs[5], 0.f);
                s1.z = fmaxf(o[6] + bs[6], 0.f);
                s1.w = fmaxf(o[7] + bs[7], 0.f);
                *reinterpret_cast<float4*>(out + (size_t)gr * D + tc * 8)     = s0;
                *reinterpret_cast<float4*>(out + (size_t)gr * D + tc * 8 + 4) = s1;
            }
        }
    }
}

// ---------------------------------------------------------------------------
extern "C" void kernel_launch(void* const* d_in, const int* in_sizes, int n_in,
                              void* d_out, int out_size) {
    const float* x = (const float*)d_in[0];
    const int* ei = (const int*)d_in[1];       // int32 (JAX x64 disabled)
    const int* batch = (const int*)d_in[2];    // int32
    const float* W1a = (const float*)d_in[3];
    const float* b1a = (const float*)d_in[4];
    const float* W1b = (const float*)d_in[5];
    const float* b1b = (const float*)d_in[6];
    const float* W2a = (const float*)d_in[7];
    const float* b2a = (const float*)d_in[8];
    const float* W2b = (const float*)d_in[9];
    const float* b2b = (const float*)d_in[10];
    const float* Wfc = (const float*)d_in[11];
    const float* bfc = (const float*)d_in[12];
    float* out = (float*)d_out;

    const int* src = ei;
    const int* dst = ei + NE;

    float *agg, *t, *h, *pool;
    int *deg, *rowptr, *cursor, *csr, *bsum, *bbase;
    cudaGetSymbolAddress((void**)&agg, g_agg);
    cudaGetSymbolAddress((void**)&t, g_t);
    cudaGetSymbolAddress((void**)&h, g_h);
    cudaGetSymbolAddress((void**)&pool, g_pool);
    cudaGetSymbolAddress((void**)&deg, g_deg);
    cudaGetSymbolAddress((void**)&rowptr, g_rowptr);
    cudaGetSymbolAddress((void**)&cursor, g_cursor);
    cudaGetSymbolAddress((void**)&csr, g_csr);
    cudaGetSymbolAddress((void**)&bsum, g_bsum);
    cudaGetSymbolAddress((void**)&bbase, g_bbase);

    const int SMEM = (128 * 128 + 64 * AS) * (int)sizeof(float); // 99328 B
    cudaFuncSetAttribute(gemm_kernel,
                         cudaFuncAttributeMaxDynamicSharedMemorySize, SMEM);

    int gemm_grid = 296;   // 2 CTAs per SM, persistent

    // CSR build (per launch; reused by both layers)
    zeroi_kernel<<<256, 256>>>(deg, NN);
    hist_kernel<<<1024, 256>>>(dst, deg);
    bsum_kernel<<<NBLK, 256>>>(deg, bsum);
    bscan_kernel<<<1, 256>>>(bsum, bbase);
    rowptr_kernel<<<NBLK, 256>>>(deg, bbase, rowptr, cursor);
    fill_kernel<<<1024, 256>>>(src, dst, cursor, csr);

    // Layer 1
    agg_kernel<<<2048, 256>>>(x, rowptr, csr, agg);
    gemm_kernel<<<gemm_grid, 256, SMEM>>>(agg, W1a, b1a, t, NN);
    gemm_kernel<<<gemm_grid, 256, SMEM>>>(t, W1b, b1b, h, NN);

    // Layer 2
    agg_kernel<<<2048, 256>>>(h, rowptr, csr, agg);
    gemm_kernel<<<gemm_grid, 256, SMEM>>>(agg, W2a, b2a, t, NN);
    gemm_kernel<<<gemm_grid, 256, SMEM>>>(t, W2b, b2b, h, NN);

    // Global add pool + FC head
    zero_kernel<<<64, 256>>>(pool, NG * D / 4);
    pool_kernel<<<2048, 256>>>(h, batch, pool);
    gemm_kernel<<<8, 256, SMEM>>>(pool, Wfc, bfc, out, NG);
}

// round 7
// speedup vs baseline: 1.8901x; 1.5611x over previous
#include <cuda_runtime.h>
#include <cuda_bf16.h>
#include <cstdint>

#define NN 50000
#define NE 800000
#define D  128
#define NG 512
#define NBLK 196 // ceil(NN/256) scan blocks

// Scratch (no device allocation allowed -> __device__ globals)
__device__ __align__(16) float g_agg[NN * D];
__device__ __align__(16) float g_t  [NN * D];
__device__ __align__(16) float g_h  [NN * D];
__device__ __align__(16) float g_pool[NG * D];
__device__ int g_deg[NN];
__device__ int g_rowptr[NN + 1];
__device__ int g_cursor[NN];
__device__ int g_csr[NE];
__device__ int g_bsum[NBLK];
__device__ int g_bbase[NBLK];

// ---------------------------------------------------------------------------
__global__ void zero_kernel(float* __restrict__ p, int n4) {
    float4 z = make_float4(0.f, 0.f, 0.f, 0.f);
    for (int i = blockIdx.x * blockDim.x + threadIdx.x; i < n4;
         i += gridDim.x * blockDim.x)
        reinterpret_cast<float4*>(p)[i] = z;
}
__global__ void zeroi_kernel(int* __restrict__ p, int n) {
    for (int i = blockIdx.x * blockDim.x + threadIdx.x; i < n;
         i += gridDim.x * blockDim.x) p[i] = 0;
}

// ---------------------------------------------------------------------------
// CSR build: histogram -> hierarchical scan -> fill
__global__ void hist_kernel(const int* __restrict__ dst, int* __restrict__ deg) {
    for (int e = blockIdx.x * blockDim.x + threadIdx.x; e < NE;
         e += gridDim.x * blockDim.x)
        atomicAdd(&deg[dst[e]], 1);
}

__global__ void bsum_kernel(const int* __restrict__ deg, int* __restrict__ bsum) {
    __shared__ int s[256];
    int i = blockIdx.x * 256 + threadIdx.x;
    s[threadIdx.x] = (i < NN) ? deg[i] : 0;
    __syncthreads();
    for (int d = 128; d > 0; d >>= 1) {
        if (threadIdx.x < d) s[threadIdx.x] += s[threadIdx.x + d];
        __syncthreads();
    }
    if (threadIdx.x == 0) bsum[blockIdx.x] = s[0];
}

__global__ void bscan_kernel(const int* __restrict__ bsum, int* __restrict__ bbase) {
    __shared__ int s[256];
    int t = threadIdx.x;
    s[t] = (t < NBLK) ? bsum[t] : 0;
    __syncthreads();
    for (int d = 1; d < 256; d <<= 1) {
        int v = (t >= d) ? s[t - d] : 0;
        __syncthreads();
        s[t] += v;
        __syncthreads();
    }
    if (t < NBLK) bbase[t] = s[t] - bsum[t];  // exclusive
}

__global__ void rowptr_kernel(const int* __restrict__ deg,
                              const int* __restrict__ bbase,
                              int* __restrict__ rowptr,
                              int* __restrict__ cursor) {
    __shared__ int s[256];
    int t = threadIdx.x;
    int i = blockIdx.x * 256 + t;
    int d0 = (i < NN) ? deg[i] : 0;
    s[t] = d0;
    __syncthreads();
    for (int d = 1; d < 256; d <<= 1) {
        int v = (t >= d) ? s[t - d] : 0;
        __syncthreads();
        s[t] += v;
        __syncthreads();
    }
    if (i < NN) {
        int off = bbase[blockIdx.x] + s[t] - d0;
        rowptr[i] = off;
        cursor[i] = off;
        if (i == NN - 1) rowptr[NN] = off + d0;
    }
}

__global__ void fill_kernel(const int* __restrict__ src,
                            const int* __restrict__ dst,
                            int* __restrict__ cursor,
                            int* __restrict__ csr) {
    for (int e = blockIdx.x * blockDim.x + threadIdx.x; e < NE;
         e += gridDim.x * blockDim.x) {
        int d = dst[e];
        int pos = atomicAdd(&cursor[d], 1);
        csr[pos] = src[e];
    }
}

// ---------------------------------------------------------------------------
// CSR aggregate: warp per node, z[n] = h[n] + sum_{s in N(n)} h[s].
__global__ void agg_kernel(const float* __restrict__ hin,
                           const int* __restrict__ rowptr,
                           const int* __restrict__ csr,
                           float* __restrict__ out) {
    int lane = threadIdx.x & 31;
    int warp = (blockIdx.x * blockDim.x + threadIdx.x) >> 5;
    int nwarp = (gridDim.x * blockDim.x) >> 5;
    for (int n = warp; n < NN; n += nwarp) {
        int beg = __ldg(&rowptr[n]), end = __ldg(&rowptr[n + 1]);
        int off = lane * 4;
        float4 a0 = *reinterpret_cast<const float4*>(hin + (size_t)n * D + off);
        float4 a1 = make_float4(0.f, 0.f, 0.f, 0.f);
        float4 a2 = make_float4(0.f, 0.f, 0.f, 0.f);
        float4 a3 = make_float4(0.f, 0.f, 0.f, 0.f);
        int k = beg;
        for (; k + 4 <= end; k += 4) {
            int s0 = __ldg(&csr[k]);
            int s1 = __ldg(&csr[k + 1]);
            int s2 = __ldg(&csr[k + 2]);
            int s3 = __ldg(&csr[k + 3]);
            float4 v0 = *reinterpret_cast<const float4*>(hin + (size_t)s0 * D + off);
            float4 v1 = *reinterpret_cast<const float4*>(hin + (size_t)s1 * D + off);
            float4 v2 = *reinterpret_cast<const float4*>(hin + (size_t)s2 * D + off);
            float4 v3 = *reinterpret_cast<const float4*>(hin + (size_t)s3 * D + off);
            a0.x += v0.x; a0.y += v0.y; a0.z += v0.z; a0.w += v0.w;
            a1.x += v1.x; a1.y += v1.y; a1.z += v1.z; a1.w += v1.w;
            a2.x += v2.x; a2.y += v2.y; a2.z += v2.z; a2.w += v2.w;
            a3.x += v3.x; a3.y += v3.y; a3.z += v3.z; a3.w += v3.w;
        }
        for (; k < end; k++) {
            int s = __ldg(&csr[k]);
            float4 v = *reinterpret_cast<const float4*>(hin + (size_t)s * D + off);
            a0.x += v.x; a0.y += v.y; a0.z += v.z; a0.w += v.w;
        }
        a0.x += a1.x + a2.x + a3.x;
        a0.y += a1.y + a2.y + a3.y;
        a0.z += a1.z + a2.z + a3.z;
        a0.w += a1.w + a2.w + a3.w;
        *reinterpret_cast<float4*>(out + (size_t)n * D + off) = a0;
    }
}

// ---------------------------------------------------------------------------
__global__ void pool_kernel(const float* __restrict__ hin,
                            const int* __restrict__ batch,
                            float* __restrict__ pool) {
    int lane = threadIdx.x & 31;
    int warp = (blockIdx.x * blockDim.x + threadIdx.x) >> 5;
    int nwarp = (gridDim.x * blockDim.x) >> 5;
    for (int n = warp; n < NN; n += nwarp) {
        int b = __ldg(&batch[n]);
        float4 v = *reinterpret_cast<const float4*>(hin + (size_t)n * D + lane * 4);
        float* p = pool + (size_t)b * D + lane * 4;
        asm volatile("red.global.add.v4.f32 [%0], {%1,%2,%3,%4};"
                     :: "l"(p), "f"(v.x), "f"(v.y), "f"(v.z), "f"(v.w)
                     : "memory");
    }
}

// ===========================================================================
// mma.sync bf16x3 GEMM: out = relu(A @ W + bias), fp32 in/out, K=N=128.
// A = Ah + Al (bf16 split); D = Ah@Wh + Al@Wh + Ah@Wl, fp32 accumulate.
// Fragments pre-packed in SMEM in mma.sync m16n8k16 register order.
// ===========================================================================

// bf16x2 pack: result = {hi:=a, lo:=b}
__device__ __forceinline__ uint32_t bf2(float hi, float lo) {
    uint32_t r;
    asm("cvt.rn.bf16x2.f32 %0, %1, %2;" : "=r"(r) : "f"(hi), "f"(lo));
    return r;
}
__device__ __forceinline__ float bfhi(uint32_t v) {           // high half as f32
    return __uint_as_float(v & 0xffff0000u);
}
__device__ __forceinline__ float bflo(uint32_t v) {           // low half as f32
    return __uint_as_float(v << 16);
}

#define MMA(c0, c1, c2, c3, a0, a1, a2, a3, b0, b1)                         \
    asm("mma.sync.aligned.m16n8k16.row.col.f32.bf16.bf16.f32 "              \
        "{%0,%1,%2,%3}, {%4,%5,%6,%7}, {%8,%9}, {%0,%1,%2,%3};"             \
        : "+f"(c0), "+f"(c1), "+f"(c2), "+f"(c3)                            \
        : "r"(a0), "r"(a1), "r"(a2), "r"(a3), "r"(b0), "r"(b1))

// SMEM layout (bytes):
//   0      bias        512
//   512    WH frag     32768   (8 ks * 16 nt * 32 lanes * 2 u32)
//   33280  WL frag     32768
//   66048  AH frag     33792   (64 groups * 33 * 16B, padded)
//   99840  AL frag     33792
#define SM_BIAS 0
#define SM_WH   512
#define SM_WL   33280
#define SM_AH   66048
#define SM_AL   99840
#define TG_SMEM 133632

__global__ __launch_bounds__(256, 1)
void tgemm_kernel(const float* __restrict__ A, const float* __restrict__ W,
                  const float* __restrict__ bias, float* __restrict__ out,
                  int M) {
    extern __shared__ char smc[];
    float*    bsm = reinterpret_cast<float*>(smc + SM_BIAS);
    uint32_t* WH  = reinterpret_cast<uint32_t*>(smc + SM_WH);
    uint32_t* WL  = reinterpret_cast<uint32_t*>(smc + SM_WL);
    uint32_t* AH  = reinterpret_cast<uint32_t*>(smc + SM_AH);
    uint32_t* AL  = reinterpret_cast<uint32_t*>(smc + SM_AL);

    int tid = threadIdx.x;
    int wid = tid >> 5;
    int lane = tid & 31;
    int lg = lane >> 2;          // fragment group (0..7)
    int lt = lane & 3;           // thread-in-group (0..3)

    // ---- Pack W fragments once: W[k][n] row-major -> mma B frag order ----
    // idx = (ks*16 + nt)*32 + lane; b0={W[k0][col],W[k0+1][col]}, b1=+8 rows
    for (int idx = tid; idx < 8 * 16 * 32; idx += 256) {
        int l = idx & 31;
        int nt = (idx >> 5) & 15;
        int ks = idx >> 9;
        int col = nt * 8 + (l >> 2);
        int k0 = ks * 16 + (l & 3) * 2;
        float w00 = __ldg(&W[(size_t)k0 * 128 + col]);
        float w01 = __ldg(&W[(size_t)(k0 + 1) * 128 + col]);
        float w10 = __ldg(&W[(size_t)(k0 + 8) * 128 + col]);
        float w11 = __ldg(&W[(size_t)(k0 + 9) * 128 + col]);
        uint32_t h0 = bf2(w01, w00);
        uint32_t h1 = bf2(w11, w10);
        uint32_t l0 = bf2(w01 - bfhi(h0), w00 - bflo(h0));
        uint32_t l1 = bf2(w11 - bfhi(h1), w10 - bflo(h1));
        WH[idx * 2]     = h0;
        WH[idx * 2 + 1] = h1;
        WL[idx * 2]     = l0;
        WL[idx * 2 + 1] = l1;
    }
    if (tid < 128) bsm[tid] = bias[tid];

    int ntiles = (M + 127) >> 7;
    for (int tile = blockIdx.x; tile < ntiles; tile += gridDim.x) {
        int row0 = tile << 7;
        __syncthreads();   // previous tile's mma reads complete

        // ---- Load A tile, split hi/lo, store in mma A-frag order ----
        // float4 per thread-iter: row r, k0..k0+3
#pragma unroll
        for (int j = 0; j < 16; j++) {
            int i4 = tid + 256 * j;
            int r = i4 >> 5;
            int q = i4 & 31;
            int k0 = q * 4;
            int gr = row0 + r;
            float4 v = make_float4(0.f, 0.f, 0.f, 0.f);
            if (gr < M)
                v = reinterpret_cast<const float4*>(A + (size_t)gr * D)[q];
            uint32_t h0 = bf2(v.y, v.x);
            uint32_t h1 = bf2(v.w, v.z);
            uint32_t l0 = bf2(v.y - bfhi(h0), v.x - bflo(h0));
            uint32_t l1 = bf2(v.w - bfhi(h1), v.z - bflo(h1));
            int mt = r >> 4;
            int g = r & 15;
            int ks = k0 >> 4;
            int kk = k0 & 15;
            int t0 = (kk & 7) >> 1;
            int reg = ((kk >= 8) ? 2 : 0) + ((g >= 8) ? 1 : 0);
            int base16 = (mt * 8 + ks) * 33 + (g & 7) * 4 + t0;
            AH[base16 * 4 + reg]       = h0;
            AH[(base16 + 1) * 4 + reg] = h1;
            AL[base16 * 4 + reg]       = l0;
            AL[(base16 + 1) * 4 + reg] = l1;
        }
        __syncthreads();

        // ---- Compute: warp wid owns rows wid*16..wid*16+15 ----
        float acc[16][4];
#pragma unroll
        for (int nt = 0; nt < 16; nt++)
#pragma unroll
            for (int j = 0; j < 4; j++) acc[nt][j] = 0.f;

#pragma unroll
        for (int ks = 0; ks < 8; ks++) {
            int ab = ((wid * 8 + ks) * 33 + lane) * 4;
            uint4 ah = *reinterpret_cast<uint4*>(&AH[ab]);
            uint4 al = *reinterpret_cast<uint4*>(&AL[ab]);
#pragma unroll
            for (int nt = 0; nt < 16; nt++) {
                int bb = ((ks * 16 + nt) * 32 + lane) * 2;
                uint2 bh = *reinterpret_cast<uint2*>(&WH[bb]);
                uint2 bl = *reinterpret_cast<uint2*>(&WL[bb]);
                MMA(acc[nt][0], acc[nt][1], acc[nt][2], acc[nt][3],
                    ah.x, ah.y, ah.z, ah.w, bh.x, bh.y);
                MMA(acc[nt][0], acc[nt][1], acc[nt][2], acc[nt][3],
                    al.x, al.y, al.z, al.w, bh.x, bh.y);
                MMA(acc[nt][0], acc[nt][1], acc[nt][2], acc[nt][3],
                    ah.x, ah.y, ah.z, ah.w, bl.x, bl.y);
            }
        }

        // ---- Epilogue: bias + relu + store ----
        int r0 = row0 + wid * 16 + lg;
        int r1 = r0 + 8;
#pragma unroll
        for (int nt = 0; nt < 16; nt++) {
            int c = nt * 8 + lt * 2;
            float b0v = bsm[c], b1v = bsm[c + 1];
            if (r0 < M) {
                float2 o;
                o.x = fmaxf(acc[nt][0] + b0v, 0.f);
                o.y = fmaxf(acc[nt][1] + b1v, 0.f);
                *reinterpret_cast<float2*>(out + (size_t)r0 * D + c) = o;
            }
            if (r1 < M) {
                float2 o;
                o.x = fmaxf(acc[nt][2] + b0v, 0.f);
                o.y = fmaxf(acc[nt][3] + b1v, 0.f);
                *reinterpret_cast<float2*>(out + (size_t)r1 * D + c) = o;
            }
        }
    }
}

// ---------------------------------------------------------------------------
extern "C" void kernel_launch(void* const* d_in, const int* in_sizes, int n_in,
                              void* d_out, int out_size) {
    const float* x = (const float*)d_in[0];
    const int* ei = (const int*)d_in[1];       // int32 (JAX x64 disabled)
    const int* batch = (const int*)d_in[2];    // int32
    const float* W1a = (const float*)d_in[3];
    const float* b1a = (const float*)d_in[4];
    const float* W1b = (const float*)d_in[5];
    const float* b1b = (const float*)d_in[6];
    const float* W2a = (const float*)d_in[7];
    const float* b2a = (const float*)d_in[8];
    const float* W2b = (const float*)d_in[9];
    const float* b2b = (const float*)d_in[10];
    const float* Wfc = (const float*)d_in[11];
    const float* bfc = (const float*)d_in[12];
    float* out = (float*)d_out;

    const int* src = ei;
    const int* dst = ei + NE;

    float *agg, *t, *h, *pool;
    int *deg, *rowptr, *cursor, *csr, *bsum, *bbase;
    cudaGetSymbolAddress((void**)&agg, g_agg);
    cudaGetSymbolAddress((void**)&t, g_t);
    cudaGetSymbolAddress((void**)&h, g_h);
    cudaGetSymbolAddress((void**)&pool, g_pool);
    cudaGetSymbolAddress((void**)&deg, g_deg);
    cudaGetSymbolAddress((void**)&rowptr, g_rowptr);
    cudaGetSymbolAddress((void**)&cursor, g_cursor);
    cudaGetSymbolAddress((void**)&csr, g_csr);
    cudaGetSymbolAddress((void**)&bsum, g_bsum);
    cudaGetSymbolAddress((void**)&bbase, g_bbase);

    cudaFuncSetAttribute(tgemm_kernel,
                         cudaFuncAttributeMaxDynamicSharedMemorySize, TG_SMEM);

    // CSR build (reused by both layers)
    zeroi_kernel<<<256, 256>>>(deg, NN);
    hist_kernel<<<1024, 256>>>(dst, deg);
    bsum_kernel<<<NBLK, 256>>>(deg, bsum);
    bscan_kernel<<<1, 256>>>(bsum, bbase);
    rowptr_kernel<<<NBLK, 256>>>(deg, bbase, rowptr, cursor);
    fill_kernel<<<1024, 256>>>(src, dst, cursor, csr);

    // Layer 1
    agg_kernel<<<2048, 256>>>(x, rowptr, csr, agg);
    tgemm_kernel<<<148, 256, TG_SMEM>>>(agg, W1a, b1a, t, NN);
    tgemm_kernel<<<148, 256, TG_SMEM>>>(t, W1b, b1b, h, NN);

    // Layer 2
    agg_kernel<<<2048, 256>>>(h, rowptr, csr, agg);
    tgemm_kernel<<<148, 256, TG_SMEM>>>(agg, W2a, b2a, t, NN);
    tgemm_kernel<<<148, 256, TG_SMEM>>>(t, W2b, b2b, h, NN);

    // Global add pool + FC head
    zero_kernel<<<64, 256>>>(pool, NG * D / 4);
    pool_kernel<<<2048, 256>>>(h, batch, pool);
    tgemm_kernel<<<4, 256, TG_SMEM>>>(pool, Wfc, bfc, out, NG);
}

// round 9
// speedup vs baseline: 2.0137x; 1.0654x over previous
#include <cuda_runtime.h>
#include <cuda_bf16.h>
#include <cstdint>

#define NN 50000
#define NE 800000
#define D  128
#define NG 512
#define NBLK 196 // ceil(NN/256) scan blocks

// Scratch (no device allocation allowed -> __device__ globals)
__device__ __align__(16) float g_agg[NN * D];
__device__ __align__(16) float g_h  [NN * D];
__device__ __align__(16) float g_pool[NG * D];
__device__ int g_deg[NN];
__device__ int g_rowptr[NN + 1];
__device__ int g_cursor[NN];
__device__ int g_csr[NE];
__device__ int g_bsum[NBLK];
__device__ int g_bbase[NBLK];

// ---------------------------------------------------------------------------
__global__ void zero_kernel(float* __restrict__ p, int n4) {
    float4 z = make_float4(0.f, 0.f, 0.f, 0.f);
    for (int i = blockIdx.x * blockDim.x + threadIdx.x; i < n4;
         i += gridDim.x * blockDim.x)
        reinterpret_cast<float4*>(p)[i] = z;
}
__global__ void zeroi_kernel(int* __restrict__ p, int n) {
    for (int i = blockIdx.x * blockDim.x + threadIdx.x; i < n;
         i += gridDim.x * blockDim.x) p[i] = 0;
}

// ---------------------------------------------------------------------------
// CSR build: histogram -> hierarchical scan -> fill
__global__ void hist_kernel(const int* __restrict__ dst, int* __restrict__ deg) {
    for (int e = blockIdx.x * blockDim.x + threadIdx.x; e < NE;
         e += gridDim.x * blockDim.x)
        atomicAdd(&deg[dst[e]], 1);
}

__global__ void bsum_kernel(const int* __restrict__ deg, int* __restrict__ bsum) {
    __shared__ int s[256];
    int i = blockIdx.x * 256 + threadIdx.x;
    s[threadIdx.x] = (i < NN) ? deg[i] : 0;
    __syncthreads();
    for (int d = 128; d > 0; d >>= 1) {
        if (threadIdx.x < d) s[threadIdx.x] += s[threadIdx.x + d];
        __syncthreads();
    }
    if (threadIdx.x == 0) bsum[blockIdx.x] = s[0];
}

// single-warp shfl scan of NBLK block sums (exclusive)
__global__ void bscan_kernel(const int* __restrict__ bsum, int* __restrict__ bbase) {
    int lane = threadIdx.x;           // 32 threads
    int v[7];                         // 32*7 >= NBLK
    int tot = 0;
#pragma unroll
    for (int i = 0; i < 7; i++) {
        int idx = lane * 7 + i;
        v[i] = (idx < NBLK) ? bsum[idx] : 0;
        tot += v[i];
    }
    int run = tot;
#pragma unroll
    for (int d = 1; d < 32; d <<= 1) {
        int u = __shfl_up_sync(0xffffffffu, run, d);
        if (lane >= d) run += u;
    }
    run -= tot;                        // exclusive across lanes
#pragma unroll
    for (int i = 0; i < 7; i++) {
        int idx = lane * 7 + i;
        if (idx < NBLK) bbase[idx] = run;
        run += v[i];
    }
}

__global__ void rowptr_kernel(const int* __restrict__ deg,
                              const int* __restrict__ bbase,
                              int* __restrict__ rowptr,
                              int* __restrict__ cursor) {
    __shared__ int s[256];
    int t = threadIdx.x;
    int i = blockIdx.x * 256 + t;
    int d0 = (i < NN) ? deg[i] : 0;
    s[t] = d0;
    __syncthreads();
    for (int d = 1; d < 256; d <<= 1) {
        int v = (t >= d) ? s[t - d] : 0;
        __syncthreads();
        s[t] += v;
        __syncthreads();
    }
    if (i < NN) {
        int off = bbase[blockIdx.x] + s[t] - d0;
        rowptr[i] = off;
        cursor[i] = off;
        if (i == NN - 1) rowptr[NN] = off + d0;
    }
}

__global__ void fill_kernel(const int* __restrict__ src,
                            const int* __restrict__ dst,
                            int* __restrict__ cursor,
                            int* __restrict__ csr) {
    for (int e = blockIdx.x * blockDim.x + threadIdx.x; e < NE;
         e += gridDim.x * blockDim.x) {
        int d = dst[e];
        int pos = atomicAdd(&cursor[d], 1);
        csr[pos] = src[e];
    }
}

// ---------------------------------------------------------------------------
// CSR aggregate: warp per node, z[n] = h[n] + sum_{s in N(n)} h[s].
__global__ void agg_kernel(const float* __restrict__ hin,
                           const int* __restrict__ rowptr,
                           const int* __restrict__ csr,
                           float* __restrict__ out) {
    int lane = threadIdx.x & 31;
    int warp = (blockIdx.x * blockDim.x + threadIdx.x) >> 5;
    int nwarp = (gridDim.x * blockDim.x) >> 5;
    for (int n = warp; n < NN; n += nwarp) {
        int beg = __ldg(&rowptr[n]), end = __ldg(&rowptr[n + 1]);
        int off = lane * 4;
        float4 a0 = *reinterpret_cast<const float4*>(hin + (size_t)n * D + off);
        float4 a1 = make_float4(0.f, 0.f, 0.f, 0.f);
        float4 a2 = make_float4(0.f, 0.f, 0.f, 0.f);
        float4 a3 = make_float4(0.f, 0.f, 0.f, 0.f);
        int k = beg;
        for (; k + 4 <= end; k += 4) {
            int s0 = __ldg(&csr[k]);
            int s1 = __ldg(&csr[k + 1]);
            int s2 = __ldg(&csr[k + 2]);
            int s3 = __ldg(&csr[k + 3]);
            float4 v0 = *reinterpret_cast<const float4*>(hin + (size_t)s0 * D + off);
            float4 v1 = *reinterpret_cast<const float4*>(hin + (size_t)s1 * D + off);
            float4 v2 = *reinterpret_cast<const float4*>(hin + (size_t)s2 * D + off);
            float4 v3 = *reinterpret_cast<const float4*>(hin + (size_t)s3 * D + off);
            a0.x += v0.x; a0.y += v0.y; a0.z += v0.z; a0.w += v0.w;
            a1.x += v1.x; a1.y += v1.y; a1.z += v1.z; a1.w += v1.w;
            a2.x += v2.x; a2.y += v2.y; a2.z += v2.z; a2.w += v2.w;
            a3.x += v3.x; a3.y += v3.y; a3.z += v3.z; a3.w += v3.w;
        }
        for (; k < end; k++) {
            int s = __ldg(&csr[k]);
            float4 v = *reinterpret_cast<const float4*>(hin + (size_t)s * D + off);
            a0.x += v.x; a0.y += v.y; a0.z += v.z; a0.w += v.w;
        }
        a0.x += a1.x + a2.x + a3.x;
        a0.y += a1.y + a2.y + a3.y;
        a0.z += a1.z + a2.z + a3.z;
        a0.w += a1.w + a2.w + a3.w;
        *reinterpret_cast<float4*>(out + (size_t)n * D + off) = a0;
    }
}

// ---------------------------------------------------------------------------
__global__ void pool_kernel(const float* __restrict__ hin,
                            const int* __restrict__ batch,
                            float* __restrict__ pool) {
    int lane = threadIdx.x & 31;
    int warp = (blockIdx.x * blockDim.x + threadIdx.x) >> 5;
    int nwarp = (gridDim.x * blockDim.x) >> 5;
    for (int n = warp; n < NN; n += nwarp) {
        int b = __ldg(&batch[n]);
        float4 v = *reinterpret_cast<const float4*>(hin + (size_t)n * D + lane * 4);
        float* p = pool + (size_t)b * D + lane * 4;
        asm volatile("red.global.add.v4.f32 [%0], {%1,%2,%3,%4};"
                     :: "l"(p), "f"(v.x), "f"(v.y), "f"(v.z), "f"(v.w)
                     : "memory");
    }
}

// ===========================================================================
// mma.sync bf16x3 helpers
// ===========================================================================
__device__ __forceinline__ uint32_t bf2(float hi, float lo) {
    uint32_t r;
    asm("cvt.rn.bf16x2.f32 %0, %1, %2;" : "=r"(r) : "f"(hi), "f"(lo));
    return r;
}
__device__ __forceinline__ float bfhi(uint32_t v) {
    return __uint_as_float(v & 0xffff0000u);
}
__device__ __forceinline__ float bflo(uint32_t v) {
    return __uint_as_float(v << 16);
}

#define MMA(c0, c1, c2, c3, a0, a1, a2, a3, b0, b1)                         \
    asm("mma.sync.aligned.m16n8k16.row.col.f32.bf16.bf16.f32 "              \
        "{%0,%1,%2,%3}, {%4,%5,%6,%7}, {%8,%9}, {%0,%1,%2,%3};"             \
        : "+f"(c0), "+f"(c1), "+f"(c2), "+f"(c3)                            \
        : "r"(a0), "r"(a1), "r"(a2), "r"(a3), "r"(b0), "r"(b1))

// Pack one weight matrix (W[k][n], 128x128 f32) into bf16 hi/lo mma-B frags.
__device__ __forceinline__ void pack_w(const float* __restrict__ W,
                                       uint32_t* WH, uint32_t* WL, int tid) {
    for (int idx = tid; idx < 8 * 16 * 32; idx += 256) {
        int l = idx & 31;
        int nt = (idx >> 5) & 15;
        int ks = idx >> 9;
        int col = nt * 8 + (l >> 2);
        int k0 = ks * 16 + (l & 3) * 2;
        float w00 = __ldg(&W[(size_t)k0 * 128 + col]);
        float w01 = __ldg(&W[(size_t)(k0 + 1) * 128 + col]);
        float w10 = __ldg(&W[(size_t)(k0 + 8) * 128 + col]);
        float w11 = __ldg(&W[(size_t)(k0 + 9) * 128 + col]);
        uint32_t h0 = bf2(w01, w00);
        uint32_t h1 = bf2(w11, w10);
        WH[idx * 2]     = h0;
        WH[idx * 2 + 1] = h1;
        WL[idx * 2]     = bf2(w01 - bfhi(h0), w00 - bflo(h0));
        WL[idx * 2 + 1] = bf2(w11 - bfhi(h1), w10 - bflo(h1));
    }
}

// ===========================================================================
// Fused MLP kernel: out = relu(relu(A@Wa+ba)@Wb+bb). Intermediate t stays in
// registers: mma C-layout == next mma A-layout, so bias+relu+bf16-split are
// pure register ops between the two passes.
// SMEM: bias 1KB | WHa/WLa/WHb/WLb 4x32KB | AH/AL 2x33KB -> 199680 B
#define F_BIAS1 0
#define F_BIAS2 512
#define F_WHA   1024
#define F_WLA   33792
#define F_WHB   66560
#define F_WLB   99328
#define F_AH    132096
#define F_AL    165888
#define F_SMEM  199680

__global__ __launch_bounds__(256, 1)
void mlp_kernel(const float* __restrict__ A,
                const float* __restrict__ Wa, const float* __restrict__ ba,
                const float* __restrict__ Wb, const float* __restrict__ bb,
                float* __restrict__ out, int M) {
    extern __shared__ char smc[];
    float*    bs1 = reinterpret_cast<float*>(smc + F_BIAS1);
    float*    bs2 = reinterpret_cast<float*>(smc + F_BIAS2);
    uint32_t* WHa = reinterpret_cast<uint32_t*>(smc + F_WHA);
    uint32_t* WLa = reinterpret_cast<uint32_t*>(smc + F_WLA);
    uint32_t* WHb = reinterpret_cast<uint32_t*>(smc + F_WHB);
    uint32_t* WLb = reinterpret_cast<uint32_t*>(smc + F_WLB);
    uint32_t* AH  = reinterpret_cast<uint32_t*>(smc + F_AH);
    uint32_t* AL  = reinterpret_cast<uint32_t*>(smc + F_AL);

    int tid = threadIdx.x;
    int wid = tid >> 5;
    int lane = tid & 31;
    int lg = lane >> 2;
    int lt = lane & 3;

    pack_w(Wa, WHa, WLa, tid);
    pack_w(Wb, WHb, WLb, tid);
    if (tid < 128) { bs1[tid] = ba[tid]; bs2[tid] = bb[tid]; }

    int ntiles = (M + 127) >> 7;
    for (int tile = blockIdx.x; tile < ntiles; tile += gridDim.x) {
        int row0 = tile << 7;
        __syncthreads();

        // ---- Load A tile, split hi/lo, store in mma A-frag order ----
#pragma unroll
        for (int j = 0; j < 16; j++) {
            int i4 = tid + 256 * j;
            int r = i4 >> 5;
            int q = i4 & 31;
            int k0 = q * 4;
            int gr = row0 + r;
            float4 v = make_float4(0.f, 0.f, 0.f, 0.f);
            if (gr < M)
                v = reinterpret_cast<const float4*>(A + (size_t)gr * D)[q];
            uint32_t h0 = bf2(v.y, v.x);
            uint32_t h1 = bf2(v.w, v.z);
            uint32_t l0 = bf2(v.y - bfhi(h0), v.x - bflo(h0));
            uint32_t l1 = bf2(v.w - bfhi(h1), v.z - bflo(h1));
            int mt = r >> 4;
            int g = r & 15;
            int ks = k0 >> 4;
            int kk = k0 & 15;
            int t0 = (kk & 7) >> 1;
            int reg = ((kk >= 8) ? 2 : 0) + ((g >= 8) ? 1 : 0);
            int base16 = (mt * 8 + ks) * 33 + (g & 7) * 4 + t0;
            AH[base16 * 4 + reg]       = h0;
            AH[(base16 + 1) * 4 + reg] = h1;
            AL[base16 * 4 + reg]       = l0;
            AL[(base16 + 1) * 4 + reg] = l1;
        }
        __syncthreads();

        // ---- Pass 1 ----
        float acc[16][4];
#pragma unroll
        for (int nt = 0; nt < 16; nt++)
#pragma unroll
            for (int j = 0; j < 4; j++) acc[nt][j] = 0.f;

#pragma unroll
        for (int ks = 0; ks < 8; ks++) {
            int ab = ((wid * 8 + ks) * 33 + lane) * 4;
            uint4 ah = *reinterpret_cast<uint4*>(&AH[ab]);
            uint4 al = *reinterpret_cast<uint4*>(&AL[ab]);
#pragma unroll
            for (int nt = 0; nt < 16; nt++) {
                int bb4 = ((ks * 16 + nt) * 32 + lane) * 2;
                uint2 bh = *reinterpret_cast<uint2*>(&WHa[bb4]);
                uint2 bl = *reinterpret_cast<uint2*>(&WLa[bb4]);
                MMA(acc[nt][0], acc[nt][1], acc[nt][2], acc[nt][3],
                    ah.x, ah.y, ah.z, ah.w, bh.x, bh.y);
                MMA(acc[nt][0], acc[nt][1], acc[nt][2], acc[nt][3],
                    al.x, al.y, al.z, al.w, bh.x, bh.y);
                MMA(acc[nt][0], acc[nt][1], acc[nt][2], acc[nt][3],
                    ah.x, ah.y, ah.z, ah.w, bl.x, bl.y);
            }
        }

        // ---- Register epilogue 1 + A-frag build for pass 2 ----
        // C layout (rows lg,lg+8 ; cols nt*8+lt*2(+1)) == A-frag layout for
        // pass-2 k-chunk ks: a0..a3 from nt=2ks (k low 8) and nt=2ks+1 (k hi 8)
        uint4 fah[8], fal[8];
#pragma unroll
        for (int ks = 0; ks < 8; ks++) {
            int nt0 = 2 * ks, nt1 = 2 * ks + 1;
            int c0 = nt0 * 8 + lt * 2;
            int c1 = nt1 * 8 + lt * 2;
            float t00 = fmaxf(acc[nt0][0] + bs1[c0],     0.f);
            float t01 = fmaxf(acc[nt0][1] + bs1[c0 + 1], 0.f);
            float t10 = fmaxf(acc[nt0][2] + bs1[c0],     0.f);
            float t11 = fmaxf(acc[nt0][3] + bs1[c0 + 1], 0.f);
            float u00 = fmaxf(acc[nt1][0] + bs1[c1],     0.f);
            float u01 = fmaxf(acc[nt1][1] + bs1[c1 + 1], 0.f);
            float u10 = fmaxf(acc[nt1][2] + bs1[c1],     0.f);
            float u11 = fmaxf(acc[nt1][3] + bs1[c1 + 1], 0.f);
            uint32_t h;
            h = bf2(t01, t00); fah[ks].x = h;
            fal[ks].x = bf2(t01 - bfhi(h), t00 - bflo(h));
            h = bf2(t11, t10); fah[ks].y = h;
            fal[ks].y = bf2(t11 - bfhi(h), t10 - bflo(h));
            h = bf2(u01, u00); fah[ks].z = h;
            fal[ks].z = bf2(u01 - bfhi(h), u00 - bflo(h));
            h = bf2(u11, u10); fah[ks].w = h;
            fal[ks].w = bf2(u11 - bfhi(h), u10 - bflo(h));
        }

        // ---- Pass 2 ----
#pragma unroll
        for (int nt = 0; nt < 16; nt++)
#pragma unroll
            for (int j = 0; j < 4; j++) acc[nt][j] = 0.f;

#pragma unroll
        for (int ks = 0; ks < 8; ks++) {
            uint4 ah = fah[ks];
            uint4 al = fal[ks];
#pragma unroll
            for (int nt = 0; nt < 16; nt++) {
                int bb4 = ((ks * 16 + nt) * 32 + lane) * 2;
                uint2 bh = *reinterpret_cast<uint2*>(&WHb[bb4]);
                uint2 bl = *reinterpret_cast<uint2*>(&WLb[bb4]);
                MMA(acc[nt][0], acc[nt][1], acc[nt][2], acc[nt][3],
                    ah.x, ah.y, ah.z, ah.w, bh.x, bh.y);
                MMA(acc[nt][0], acc[nt][1], acc[nt][2], acc[nt][3],
                    al.x, al.y, al.z, al.w, bh.x, bh.y);
                MMA(acc[nt][0], acc[nt][1], acc[nt][2], acc[nt][3],
                    ah.x, ah.y, ah.z, ah.w, bl.x, bl.y);
            }
        }

        // ---- Epilogue 2: bias + relu + store ----
        int r0 = row0 + wid * 16 + lg;
        int r1 = r0 + 8;
#pragma unroll
        for (int nt = 0; nt < 16; nt++) {
            int c = nt * 8 + lt * 2;
            float b0v = bs2[c], b1v = bs2[c + 1];
            if (r0 < M) {
                float2 o;
                o.x = fmaxf(acc[nt][0] + b0v, 0.f);
                o.y = fmaxf(acc[nt][1] + b1v, 0.f);
                *reinterpret_cast<float2*>(out + (size_t)r0 * D + c) = o;
            }
            if (r1 < M) {
                float2 o;
                o.x = fmaxf(acc[nt][2] + b0v, 0.f);
                o.y = fmaxf(acc[nt][3] + b1v, 0.f);
                *reinterpret_cast<float2*>(out + (size_t)r1 * D + c) = o;
            }
        }
    }
}

// ===========================================================================
// Single GEMM (for FC head): out = relu(A@W + bias)
#define SM_BIAS 0
#define SM_WH   512
#define SM_WL   33280
#define SM_AH   66048
#define SM_AL   99840
#define TG_SMEM 133632

__global__ __launch_bounds__(256, 1)
void tgemm_kernel(const float* __restrict__ A, const float* __restrict__ W,
                  const float* __restrict__ bias, float* __restrict__ out,
                  int M) {
    extern __shared__ char smc[];
    float*    bsm = reinterpret_cast<float*>(smc + SM_BIAS);
    uint32_t* WH  = reinterpret_cast<uint32_t*>(smc + SM_WH);
    uint32_t* WL  = reinterpret_cast<uint32_t*>(smc + SM_WL);
    uint32_t* AH  = reinterpret_cast<uint32_t*>(smc + SM_AH);
    uint32_t* AL  = reinterpret_cast<uint32_t*>(smc + SM_AL);

    int tid = threadIdx.x;
    int wid = tid >> 5;
    int lane = tid & 31;
    int lg = lane >> 2;
    int lt = lane & 3;

    pack_w(W, WH, WL, tid);
    if (tid < 128) bsm[tid] = bias[tid];

    int ntiles = (M + 127) >> 7;
    for (int tile = blockIdx.x; tile < ntiles; tile += gridDim.x) {
        int row0 = tile << 7;
        __syncthreads();
#pragma unroll
        for (int j = 0; j < 16; j++) {
            int i4 = tid + 256 * j;
            int r = i4 >> 5;
            int q = i4 & 31;
            int k0 = q * 4;
            int gr = row0 + r;
            float4 v = make_float4(0.f, 0.f, 0.f, 0.f);
            if (gr < M)
                v = reinterpret_cast<const float4*>(A + (size_t)gr * D)[q];
            uint32_t h0 = bf2(v.y, v.x);
            uint32_t h1 = bf2(v.w, v.z);
            uint32_t l0 = bf2(v.y - bfhi(h0), v.x - bflo(h0));
            uint32_t l1 = bf2(v.w - bfhi(h1), v.z - bflo(h1));
            int mt = r >> 4;
            int g = r & 15;
            int ks = k0 >> 4;
            int kk = k0 & 15;
            int t0 = (kk & 7) >> 1;
            int reg = ((kk >= 8) ? 2 : 0) + ((g >= 8) ? 1 : 0);
            int base16 = (mt * 8 + ks) * 33 + (g & 7) * 4 + t0;
            AH[base16 * 4 + reg]       = h0;
            AH[(base16 + 1) * 4 + reg] = h1;
            AL[base16 * 4 + reg]       = l0;
            AL[(base16 + 1) * 4 + reg] = l1;
        }
        __syncthreads();

        float acc[16][4];
#pragma unroll
        for (int nt = 0; nt < 16; nt++)
#pragma unroll
            for (int j = 0; j < 4; j++) acc[nt][j] = 0.f;

#pragma unroll
        for (int ks = 0; ks < 8; ks++) {
            int ab = ((wid * 8 + ks) * 33 + lane) * 4;
            uint4 ah = *reinterpret_cast<uint4*>(&AH[ab]);
            uint4 al = *reinterpret_cast<uint4*>(&AL[ab]);
#pragma unroll
            for (int nt = 0; nt < 16; nt++) {
                int bb4 = ((ks * 16 + nt) * 32 + lane) * 2;
                uint2 bh = *reinterpret_cast<uint2*>(&WH[bb4]);
                uint2 bl = *reinterpret_cast<uint2*>(&WL[bb4]);
                MMA(acc[nt][0], acc[nt][1], acc[nt][2], acc[nt][3],
                    ah.x, ah.y, ah.z, ah.w, bh.x, bh.y);
                MMA(acc[nt][0], acc[nt][1], acc[nt][2], acc[nt][3],
                    al.x, al.y, al.z, al.w, bh.x, bh.y);
                MMA(acc[nt][0], acc[nt][1], acc[nt][2], acc[nt][3],
                    ah.x, ah.y, ah.z, ah.w, bl.x, bl.y);
            }
        }

        int r0 = row0 + wid * 16 + lg;
        int r1 = r0 + 8;
#pragma unroll
        for (int nt = 0; nt < 16; nt++) {
            int c = nt * 8 + lt * 2;
            float b0v = bsm[c], b1v = bsm[c + 1];
            if (r0 < M) {
                float2 o;
                o.x = fmaxf(acc[nt][0] + b0v, 0.f);
                o.y = fmaxf(acc[nt][1] + b1v, 0.f);
                *reinterpret_cast<float2*>(out + (size_t)r0 * D + c) = o;
            }
            if (r1 < M) {
                float2 o;
                o.x = fmaxf(acc[nt][2] + b0v, 0.f);
                o.y = fmaxf(acc[nt][3] + b1v, 0.f);
                *reinterpret_cast<float2*>(out + (size_t)r1 * D + c) = o;
            }
        }
    }
}

// ---------------------------------------------------------------------------
extern "C" void kernel_launch(void* const* d_in, const int* in_sizes, int n_in,
                              void* d_out, int out_size) {
    const float* x = (const float*)d_in[0];
    const int* ei = (const int*)d_in[1];       // int32 (JAX x64 disabled)
    const int* batch = (const int*)d_in[2];    // int32
    const float* W1a = (const float*)d_in[3];
    const float* b1a = (const float*)d_in[4];
    const float* W1b = (const float*)d_in[5];
    const float* b1b = (const float*)d_in[6];
    const float* W2a = (const float*)d_in[7];
    const float* b2a = (const float*)d_in[8];
    const float* W2b = (const float*)d_in[9];
    const float* b2b = (const float*)d_in[10];
    const float* Wfc = (const float*)d_in[11];
    const float* bfc = (const float*)d_in[12];
    float* out = (float*)d_out;

    const int* src = ei;
    const int* dst = ei + NE;

    float *agg, *h, *pool;
    int *deg, *rowptr, *cursor, *csr, *bsum, *bbase;
    cudaGetSymbolAddress((void**)&agg, g_agg);
    cudaGetSymbolAddress((void**)&h, g_h);
    cudaGetSymbolAddress((void**)&pool, g_pool);
    cudaGetSymbolAddress((void**)&deg, g_deg);
    cudaGetSymbolAddress((void**)&rowptr, g_rowptr);
    cudaGetSymbolAddress((void**)&cursor, g_cursor);
    cudaGetSymbolAddress((void**)&csr, g_csr);
    cudaGetSymbolAddress((void**)&bsum, g_bsum);
    cudaGetSymbolAddress((void**)&bbase, g_bbase);

    cudaFuncSetAttribute(mlp_kernel,
                         cudaFuncAttributeMaxDynamicSharedMemorySize, F_SMEM);
    cudaFuncSetAttribute(tgemm_kernel,
                         cudaFuncAttributeMaxDynamicSharedMemorySize, TG_SMEM);

    // CSR build (reused by both layers)
    zeroi_kernel<<<256, 256>>>(deg, NN);
    hist_kernel<<<1024, 256>>>(dst, deg);
    bsum_kernel<<<NBLK, 256>>>(deg, bsum);
    bscan_kernel<<<1, 32>>>(bsum, bbase);
    rowptr_kernel<<<NBLK, 256>>>(deg, bbase, rowptr, cursor);
    fill_kernel<<<1024, 256>>>(src, dst, cursor, csr);

    // Layer 1: agg then fused MLP
    agg_kernel<<<2048, 256>>>(x, rowptr, csr, agg);
    mlp_kernel<<<148, 256, F_SMEM>>>(agg, W1a, b1a, W1b, b1b, h, NN);

    // Layer 2
    agg_kernel<<<2048, 256>>>(h, rowptr, csr, agg);
    mlp_kernel<<<148, 256, F_SMEM>>>(agg, W2a, b2a, W2b, b2b, h, NN);

    // Global add pool + FC head
    zero_kernel<<<64, 256>>>(pool, NG * D / 4);
    pool_kernel<<<2048, 256>>>(h, batch, pool);
    tgemm_kernel<<<4, 256, TG_SMEM>>>(pool, Wfc, bfc, out, NG);
}